// round 10
// baseline (speedup 1.0000x reference)
#include <cuda_runtime.h>

#define Bn    16
#define Nn    9216
#define Cn    256
#define Kn    21
#define ITERS 20
#define TILES 9          /* Nn / 1024 points per assign block */
#define SUBS  4          /* 256-point sub-chunks per tile (Eigen kc=256) */
#define NCHUNK (TILES * SUBS)

// ---------------- device scratch (no allocations allowed) ----------------
__device__ float g_xT[(size_t)Bn * Cn * Nn];              // x transposed [b][c][n]
__device__ float g_cent[Bn * Kn * Cn];                    // centroids [b][k][c]
__device__ float g_csq[Bn * Kn];                          // ||c_k||^2, sequential order
__device__ float g_psums[(size_t)NCHUNK * Bn * Kn * Cn];  // per-256-chunk partial sums
__device__ int   g_pcnt[TILES * Bn * Kn];                 // per-tile partial counts
__device__ int   g_i64;                                   // 1 if init_idx is int64

// ---------------- dtype detector for init_idx (int64 vs int32) ----------------
__global__ void detect_kernel(const unsigned long long* __restrict__ idx) {
    if (threadIdx.x == 0 && blockIdx.x == 0) {
        int f = 1;
        // Read exactly 1344 bytes = sizeof(init_idx) under either dtype.
        for (int i = 0; i < (Bn * Kn) / 2; i++)
            if (idx[i] >= (unsigned long long)Nn) f = 0;
        g_i64 = f;
    }
}

// ---------------- transpose x[b][n][c] -> g_xT[b][c][n] (exact copy) ----------------
__global__ void transpose_kernel(const float* __restrict__ x) {
    __shared__ float t[32][33];
    int b  = blockIdx.z;
    int n0 = blockIdx.x * 32, c0 = blockIdx.y * 32;
    int tx = threadIdx.x, ty = threadIdx.y;
#pragma unroll
    for (int r = 0; r < 4; r++)
        t[ty + 8 * r][tx] = x[(size_t)(b * Nn + n0 + ty + 8 * r) * Cn + c0 + tx];
    __syncthreads();
#pragma unroll
    for (int r = 0; r < 4; r++)
        g_xT[(size_t)(b * Cn + c0 + ty + 8 * r) * Nn + n0 + tx] = t[tx][ty + 8 * r];
}

// ---------------- initial centroids: gather + sequential unfused ||c||^2 ----------------
__global__ void init_kernel(const float* __restrict__ x, const void* __restrict__ idxp) {
    __shared__ float sv[Cn];
    int bk = blockIdx.x;              // b*Kn + k
    int b  = bk / Kn;
    int tid = threadIdx.x;
    long long n;
    if (g_i64) n = ((const long long*)idxp)[bk];
    else       n = (long long)((const int*)idxp)[bk];
    float v = x[(size_t)(b * Nn + (int)n) * Cn + tid];
    g_cent[bk * Cn + tid] = v;
    sv[tid] = v;
    __syncthreads();
    if (tid == 0) {
        float s = 0.f;                 // square-then-add, strictly ascending c
        for (int c = 0; c < Cn; c++)
            s = __fadd_rn(s, __fmul_rn(sv[c], sv[c]));
        g_csq[bk] = s;
    }
}

// ---------------- fused assignment + per-256-chunk scatter-sum ----------------
__global__ __launch_bounds__(256, 1) void assign_kernel(const float* __restrict__ x) {
    __shared__ float4        sc[Cn][6];      // centroids channel-major, K padded to 24
    __shared__ float         ssum[Kn][Cn];   // per-sub-chunk partial sums
    __shared__ float         scsq[Kn];
    __shared__ int           scnt[Kn];
    __shared__ unsigned char sasg[1024];

    int b = blockIdx.y, tile = blockIdx.x, tid = threadIdx.x;

    // Stage centroids transposed: sc[c][kq].{x..w} = cent[4kq+j][c]
    float* scf = (float*)&sc[tid][0];
#pragma unroll
    for (int k = 0; k < Kn; k++) scf[k] = g_cent[(b * Kn + k) * Cn + tid];
    scf[21] = 0.f; scf[22] = 0.f; scf[23] = 0.f;
    if (tid < Kn) { scsq[tid] = g_csq[b * Kn + tid]; scnt[tid] = 0; }
#pragma unroll
    for (int k = 0; k < Kn; k++) ssum[k][tid] = 0.f;
    __syncthreads();

    // ---- phase 1: dot (ascending-c FFMA chain, Eigen-like) + x_sq (unfused seq) ----
    const float4* xT4 = (const float4*)(g_xT + (size_t)b * Cn * Nn);
    int pq = (tile * 1024 + tid * 4) >> 2;

    float4 a0[6], a1[6], a2[6], a3[6];
#pragma unroll
    for (int q = 0; q < 6; q++) {
        a0[q] = make_float4(0.f, 0.f, 0.f, 0.f);
        a1[q] = make_float4(0.f, 0.f, 0.f, 0.f);
        a2[q] = make_float4(0.f, 0.f, 0.f, 0.f);
        a3[q] = make_float4(0.f, 0.f, 0.f, 0.f);
    }
    float xsq0 = 0.f, xsq1 = 0.f, xsq2 = 0.f, xsq3 = 0.f;

#pragma unroll 2
    for (int c = 0; c < Cn; c++) {
        float4 xv = xT4[c * (Nn / 4) + pq];          // coalesced LDG.128
        // x_sq: square (rounded) then add (rounded), strictly ascending c
        xsq0 = __fadd_rn(xsq0, __fmul_rn(xv.x, xv.x));
        xsq1 = __fadd_rn(xsq1, __fmul_rn(xv.y, xv.y));
        xsq2 = __fadd_rn(xsq2, __fmul_rn(xv.z, xv.z));
        xsq3 = __fadd_rn(xsq3, __fmul_rn(xv.w, xv.w));
        float4 cw = sc[c][0];
#pragma unroll
        for (int q = 0; q < 6; q++) {
            float4 cwn;
            if (q < 5) cwn = sc[c][q + 1];            // prefetch next k-quad (ILP)
            a0[q].x = __fmaf_rn(xv.x, cw.x, a0[q].x); a0[q].y = __fmaf_rn(xv.x, cw.y, a0[q].y);
            a0[q].z = __fmaf_rn(xv.x, cw.z, a0[q].z); a0[q].w = __fmaf_rn(xv.x, cw.w, a0[q].w);
            a1[q].x = __fmaf_rn(xv.y, cw.x, a1[q].x); a1[q].y = __fmaf_rn(xv.y, cw.y, a1[q].y);
            a1[q].z = __fmaf_rn(xv.y, cw.z, a1[q].z); a1[q].w = __fmaf_rn(xv.y, cw.w, a1[q].w);
            a2[q].x = __fmaf_rn(xv.z, cw.x, a2[q].x); a2[q].y = __fmaf_rn(xv.z, cw.y, a2[q].y);
            a2[q].z = __fmaf_rn(xv.z, cw.z, a2[q].z); a2[q].w = __fmaf_rn(xv.z, cw.w, a2[q].w);
            a3[q].x = __fmaf_rn(xv.w, cw.x, a3[q].x); a3[q].y = __fmaf_rn(xv.w, cw.y, a3[q].y);
            a3[q].z = __fmaf_rn(xv.w, cw.z, a3[q].z); a3[q].w = __fmaf_rn(xv.w, cw.w, a3[q].w);
            cw = cwn;
        }
    }

    // ---- argmin over d = fl(fl(x_sq - 2*dot) + csq), reference association ----
    float rcsq[Kn];
#pragma unroll
    for (int k = 0; k < Kn; k++) rcsq[k] = scsq[k];

#define DO_ARGMIN(ACC, XSQ, P)                                             \
    {                                                                      \
        const float* ap = (const float*)ACC;                               \
        float best = __fadd_rn(__fadd_rn(XSQ, -__fmul_rn(2.f, ap[0])),     \
                               rcsq[0]);                                   \
        int   bi = 0;                                                      \
        _Pragma("unroll")                                                  \
        for (int k = 1; k < Kn; k++) {                                     \
            float d = __fadd_rn(__fadd_rn(XSQ, -__fmul_rn(2.f, ap[k])),    \
                                rcsq[k]);                                  \
            if (d < best) { best = d; bi = k; }                            \
        }                                                                  \
        sasg[tid * 4 + (P)] = (unsigned char)bi;                           \
        atomicAdd(&scnt[bi], 1);                                           \
    }
    DO_ARGMIN(a0, xsq0, 0)
    DO_ARGMIN(a1, xsq1, 1)
    DO_ARGMIN(a2, xsq2, 2)
    DO_ARGMIN(a3, xsq3, 3)
#undef DO_ARGMIN
    __syncthreads();

    // ---- phase 2: Eigen-style 256-point panels (thread = channel) ----
    // Within each panel: strictly sequential ascending n, register-carried
    // running value (bitwise identical to sequential smem adds). Panels are
    // flushed separately and combined ascending in update_kernel.
    const float* xrow = x + (size_t)(b * Nn + tile * 1024) * Cn + tid;
    for (int s = 0; s < SUBS; s++) {
        int n0 = s * 256;
        int aprev = sasg[n0];
        float racc = 0.f;              // ssum rows are zero at panel start
        for (int q = 0; q < 256; q += 8) {
            float v[8];
#pragma unroll
            for (int j = 0; j < 8; j++)
                v[j] = __ldg(xrow + (size_t)(n0 + q + j) * Cn);
#pragma unroll
            for (int j = 0; j < 8; j++) {
                int a = sasg[n0 + q + j];
                if (a != aprev) {
                    ssum[aprev][tid] = racc;
                    racc = ssum[a][tid];
                    aprev = a;
                }
                racc = __fadd_rn(racc, v[j]);
            }
        }
        ssum[aprev][tid] = racc;
        __syncthreads();
        size_t base = (size_t)(((tile * SUBS + s) * Bn + b) * Kn) * Cn;
#pragma unroll
        for (int k = 0; k < Kn; k++) {
            g_psums[base + k * Cn + tid] = ssum[k][tid];
            ssum[k][tid] = 0.f;        // re-zero for next panel
        }
        __syncthreads();
    }

    if (tid < Kn) g_pcnt[(tile * Bn + b) * Kn + tid] = scnt[tid];
}

// ---------------- centroid update + sequential unfused ||c||^2 ----------------
__global__ void update_kernel(float* __restrict__ out) {
    __shared__ float scn[Cn];
    int bk = blockIdx.x;
    int tid = threadIdx.x;
    float s = 0.f;
    int cnt = 0;
#pragma unroll
    for (int t = 0; t < NCHUNK; t++)           // 36 panels, ascending n
        s = __fadd_rn(s, g_psums[(size_t)(t * Bn * Kn + bk) * Cn + tid]);
#pragma unroll
    for (int t = 0; t < TILES; t++)
        cnt += g_pcnt[t * Bn * Kn + bk];
    float oldc = g_cent[bk * Cn + tid];
    float cn = (cnt > 0) ? __fdiv_rn(s, (float)cnt) : oldc;   // exact rn divide
    g_cent[bk * Cn + tid] = cn;
    if (out) out[bk * Cn + tid] = cn;
    scn[tid] = cn;
    __syncthreads();
    if (tid == 0) {
        float q = 0.f;                 // square-then-add, strictly ascending c
        for (int c = 0; c < Cn; c++)
            q = __fadd_rn(q, __fmul_rn(scn[c], scn[c]));
        g_csq[bk] = q;
    }
}

// ---------------- launch ----------------
extern "C" void kernel_launch(void* const* d_in, const int* in_sizes, int n_in,
                              void* d_out, int out_size) {
    const float* x   = (const float*)d_in[0];
    const void*  idx = d_in[1];

    detect_kernel<<<1, 32>>>((const unsigned long long*)idx);
    init_kernel<<<Bn * Kn, 256>>>(x, idx);
    transpose_kernel<<<dim3(Nn / 32, Cn / 32, Bn), dim3(32, 8)>>>(x);

    for (int it = 0; it < ITERS; ++it) {
        assign_kernel<<<dim3(TILES, Bn), 256>>>(x);
        update_kernel<<<Bn * Kn, 256>>>(it == ITERS - 1 ? (float*)d_out : nullptr);
    }
}

// round 12
// speedup vs baseline: 1.7179x; 1.7179x over previous
#include <cuda_runtime.h>

#define Bn     16
#define Nn     9216
#define Cn     256
#define Kn     21
#define ITERS  20
#define PANELS 36        /* 256-point panels; one panel per assign block */

// ---------------- device scratch (no allocations allowed) ----------------
__device__ float g_xT[(size_t)Bn * Cn * Nn];               // x transposed [b][c][n]
__device__ float g_xsq[(size_t)Bn * Nn];                   // ||x_n||^2, seq unfused asc-c
__device__ float g_cent[Bn * Kn * Cn];                     // centroids [b][k][c]
__device__ float g_csq[Bn * Kn];                           // ||c_k||^2, seq unfused asc-c
__device__ float g_psums[(size_t)PANELS * Bn * Kn * Cn];   // per-panel partial sums
__device__ int   g_pcnt[PANELS * Bn * Kn];                 // per-panel partial counts
__device__ int   g_i64;                                    // 1 if init_idx is int64

// ---------------- dtype detector for init_idx (int64 vs int32) ----------------
__global__ void detect_kernel(const unsigned long long* __restrict__ idx) {
    if (threadIdx.x == 0 && blockIdx.x == 0) {
        int f = 1;
        // Read exactly 1344 bytes = sizeof(init_idx) under either dtype.
        for (int i = 0; i < (Bn * Kn) / 2; i++)
            if (idx[i] >= (unsigned long long)Nn) f = 0;
        g_i64 = f;
    }
}

// ---------------- x_sq: 1 thread per point, seq unfused ascending-c ----------------
__global__ void xsq_kernel(const float* __restrict__ x) {
    long long P = (long long)blockIdx.x * 256 + threadIdx.x;   // over Bn*Nn
    const float4* row4 = (const float4*)(x + (size_t)P * Cn);
    float s = 0.f;
#pragma unroll 8
    for (int i = 0; i < Cn / 4; i++) {
        float4 v = row4[i];
        s = __fadd_rn(s, __fmul_rn(v.x, v.x));
        s = __fadd_rn(s, __fmul_rn(v.y, v.y));
        s = __fadd_rn(s, __fmul_rn(v.z, v.z));
        s = __fadd_rn(s, __fmul_rn(v.w, v.w));
    }
    g_xsq[P] = s;
}

// ---------------- transpose x[b][n][c] -> g_xT[b][c][n] (exact copy) ----------------
__global__ void transpose_kernel(const float* __restrict__ x) {
    __shared__ float t[32][33];
    int b  = blockIdx.z;
    int n0 = blockIdx.x * 32, c0 = blockIdx.y * 32;
    int tx = threadIdx.x, ty = threadIdx.y;
#pragma unroll
    for (int r = 0; r < 4; r++)
        t[ty + 8 * r][tx] = x[(size_t)(b * Nn + n0 + ty + 8 * r) * Cn + c0 + tx];
    __syncthreads();
#pragma unroll
    for (int r = 0; r < 4; r++)
        g_xT[(size_t)(b * Cn + c0 + ty + 8 * r) * Nn + n0 + tx] = t[tx][ty + 8 * r];
}

// ---------------- initial centroids: gather + sequential unfused ||c||^2 ----------------
__global__ void init_kernel(const float* __restrict__ x, const void* __restrict__ idxp) {
    __shared__ float sv[Cn];
    int bk = blockIdx.x;              // b*Kn + k
    int b  = bk / Kn;
    int tid = threadIdx.x;
    long long n;
    if (g_i64) n = ((const long long*)idxp)[bk];
    else       n = (long long)((const int*)idxp)[bk];
    float v = x[(size_t)(b * Nn + (int)n) * Cn + tid];
    g_cent[bk * Cn + tid] = v;
    sv[tid] = v;
    __syncthreads();
    if (tid == 0) {
        float s = 0.f;                 // square-then-add, strictly ascending c
        for (int c = 0; c < Cn; c++)
            s = __fadd_rn(s, __fmul_rn(sv[c], sv[c]));
        g_csq[bk] = s;
    }
}

// ---------------- fused assignment + per-panel scatter-sum ----------------
// One 256-point panel per block, one point per thread, 4 CTAs/SM.
__global__ __launch_bounds__(256, 4) void assign_kernel(const float* __restrict__ x) {
    __shared__ float         sc[Cn][24];     // centroids channel-major (21 used, pad 24)
    __shared__ float         ssum[Kn][Cn];   // per-panel partial sums
    __shared__ float         scsq[Kn];
    __shared__ int           scnt[Kn];
    __shared__ unsigned char sasg[256];

    int b = blockIdx.y, p = blockIdx.x, tid = threadIdx.x;

    // Stage centroids transposed: sc[c][k] = cent[k][c]
#pragma unroll
    for (int k = 0; k < Kn; k++) sc[tid][k] = g_cent[(b * Kn + k) * Cn + tid];
    sc[tid][21] = 0.f; sc[tid][22] = 0.f; sc[tid][23] = 0.f;
    if (tid < Kn) { scsq[tid] = g_csq[b * Kn + tid]; scnt[tid] = 0; }
#pragma unroll
    for (int k = 0; k < Kn; k++) ssum[k][tid] = 0.f;
    __syncthreads();

    // ---- phase 1: dot for ONE point, ascending-c FFMA chain ----
    int n = p * 256 + tid;
    const float* xTb = g_xT + (size_t)b * Cn * Nn;
    float xsq = g_xsq[(size_t)b * Nn + n];

    float4 a[5];                       // k = 0..19
    float  a20 = 0.f;                  // k = 20
#pragma unroll
    for (int q = 0; q < 5; q++) a[q] = make_float4(0.f, 0.f, 0.f, 0.f);

#pragma unroll 2
    for (int c = 0; c < Cn; c++) {
        float xv = xTb[(size_t)c * Nn + n];          // coalesced 128B per warp
        const float4* cw4 = (const float4*)&sc[c][0];
#pragma unroll
        for (int q = 0; q < 5; q++) {
            float4 cw = cw4[q];                       // broadcast LDS.128
            a[q].x = __fmaf_rn(xv, cw.x, a[q].x);
            a[q].y = __fmaf_rn(xv, cw.y, a[q].y);
            a[q].z = __fmaf_rn(xv, cw.z, a[q].z);
            a[q].w = __fmaf_rn(xv, cw.w, a[q].w);
        }
        a20 = __fmaf_rn(xv, sc[c][20], a20);
    }

    // ---- argmin over d = fl(fl(x_sq - 2*dot) + csq), ascending k, first-min ----
    {
        const float* ap = (const float*)a;            // k = 0..19 contiguous
        float best = __fadd_rn(__fadd_rn(xsq, -__fmul_rn(2.f, ap[0])), scsq[0]);
        int   bi = 0;
#pragma unroll
        for (int k = 1; k < 20; k++) {
            float d = __fadd_rn(__fadd_rn(xsq, -__fmul_rn(2.f, ap[k])), scsq[k]);
            if (d < best) { best = d; bi = k; }
        }
        {
            float d = __fadd_rn(__fadd_rn(xsq, -__fmul_rn(2.f, a20)), scsq[20]);
            if (d < best) { best = d; bi = 20; }
        }
        sasg[tid] = (unsigned char)bi;
        atomicAdd(&scnt[bi], 1);
    }
    __syncthreads();

    // ---- phase 2: one 256-point panel, strictly sequential ascending n ----
    // thread = channel; register-carried running value, bitwise identical to
    // sequential smem adds. Reads original x (coalesced per point).
    const float* xrow = x + (size_t)(b * Nn + p * 256) * Cn + tid;
    int aprev = sasg[0];
    float racc = 0.f;                  // ssum rows start at 0
    for (int q = 0; q < 256; q += 8) {
        float v[8];
#pragma unroll
        for (int j = 0; j < 8; j++) v[j] = __ldg(xrow + (size_t)(q + j) * Cn);
#pragma unroll
        for (int j = 0; j < 8; j++) {
            int a2 = sasg[q + j];
            if (a2 != aprev) {
                ssum[aprev][tid] = racc;
                racc = ssum[a2][tid];
                aprev = a2;
            }
            racc = __fadd_rn(racc, v[j]);
        }
    }
    ssum[aprev][tid] = racc;
    __syncthreads();

    // ---- deterministic panel writeback (plain stores, no global atomics) ----
    size_t base = (size_t)((p * Bn + b) * Kn) * Cn;
#pragma unroll
    for (int k = 0; k < Kn; k++) g_psums[base + k * Cn + tid] = ssum[k][tid];
    if (tid < Kn) g_pcnt[(p * Bn + b) * Kn + tid] = scnt[tid];
}

// ---------------- centroid update + sequential unfused ||c||^2 ----------------
__global__ void update_kernel(float* __restrict__ out) {
    __shared__ float scn[Cn];
    int bk = blockIdx.x;
    int tid = threadIdx.x;
    float s = 0.f;
    int cnt = 0;
#pragma unroll
    for (int t = 0; t < PANELS; t++) {         // 36 panels, ascending n
        s = __fadd_rn(s, g_psums[(size_t)(t * Bn * Kn + bk) * Cn + tid]);
        cnt += g_pcnt[t * Bn * Kn + bk];
    }
    float oldc = g_cent[bk * Cn + tid];
    float cn = (cnt > 0) ? __fdiv_rn(s, (float)cnt) : oldc;   // exact rn divide
    g_cent[bk * Cn + tid] = cn;
    if (out) out[bk * Cn + tid] = cn;
    scn[tid] = cn;
    __syncthreads();
    if (tid == 0) {
        float q = 0.f;                 // square-then-add, strictly ascending c
        for (int c = 0; c < Cn; c++)
            q = __fadd_rn(q, __fmul_rn(scn[c], scn[c]));
        g_csq[bk] = q;
    }
}

// ---------------- launch ----------------
extern "C" void kernel_launch(void* const* d_in, const int* in_sizes, int n_in,
                              void* d_out, int out_size) {
    const float* x   = (const float*)d_in[0];
    const void*  idx = d_in[1];

    detect_kernel<<<1, 32>>>((const unsigned long long*)idx);
    init_kernel<<<Bn * Kn, 256>>>(x, idx);
    xsq_kernel<<<(Bn * Nn) / 256, 256>>>(x);
    transpose_kernel<<<dim3(Nn / 32, Cn / 32, Bn), dim3(32, 8)>>>(x);

    for (int it = 0; it < ITERS; ++it) {
        assign_kernel<<<dim3(PANELS, Bn), 256>>>(x);
        update_kernel<<<Bn * Kn, 256>>>(it == ITERS - 1 ? (float*)d_out : nullptr);
    }
}